// round 15
// baseline (speedup 1.0000x reference)
#include <cuda_runtime.h>
#include <cuda_fp16.h>
#include <cstdint>

#define NF 128
#define NH 64
#define MAXN 50000
#define MAXE 800000

// Scratch (allocation-free rule: __device__ globals)
__device__ __half2 g_zh[(size_t)MAXN * (NH / 2)];   // 6.4 MB, z in fp16
__device__ float g_sd[MAXN];
__device__ float g_ss[MAXN];
__device__ int   g_dst[MAXE];
__device__ int   g_src[MAXE];
__device__ int   g_cnt[MAXN];
__device__ int   g_rowstart[MAXN];
__device__ int   g_cursor[MAXN];
__device__ int   g_bsum[1024];
__device__ int2  g_csr[MAXE];              // {src, eidx} — h computed in aggregate
__device__ int   g_is32;

// ---------------------------------------------------------------------------
__global__ void zero_kernel(int n_nodes) {
    int i = blockIdx.x * blockDim.x + threadIdx.x;
    if (i < n_nodes) g_cnt[i] = 0;
    if (i == 0) g_is32 = 0;
}

// dtype probe: scan first 4096 odd words; int64 (<2^31 values) -> all zero.
__global__ void detect_kernel(const int* __restrict__ w, int nelem) {
    int found = 0;
    int lim = nelem / 2;
    if (lim > 4096) lim = 4096;
    for (int i = threadIdx.x; i < lim; i += 256)
        found |= w[2 * i + 1];
    if (__syncthreads_or(found) && threadIdx.x == 0) g_is32 = 1;
}

// Convert to int32 + histogram, 4 edges per thread, vector loads/stores.
__global__ void convert_kernel(const void* __restrict__ ei, int E) {
    int t = blockIdx.x * blockDim.x + threadIdx.x;
    int base = t * 4;
    if (base >= E) return;
    if (base + 3 < E && (E & 3) == 0) {
        int4 d4, s4;
        if (g_is32) {
            const int4* p = (const int4*)ei;
            d4 = p[base >> 2];
            s4 = p[(E + base) >> 2];
        } else {
            const longlong2* p = (const longlong2*)ei;
            longlong2 a0 = p[(base >> 1)];
            longlong2 a1 = p[(base >> 1) + 1];
            longlong2 b0 = p[((E + base) >> 1)];
            longlong2 b1 = p[((E + base) >> 1) + 1];
            d4 = make_int4((int)a0.x, (int)a0.y, (int)a1.x, (int)a1.y);
            s4 = make_int4((int)b0.x, (int)b0.y, (int)b1.x, (int)b1.y);
        }
        *reinterpret_cast<int4*>(&g_dst[base]) = d4;
        *reinterpret_cast<int4*>(&g_src[base]) = s4;
        atomicAdd(&g_cnt[d4.x], 1);
        atomicAdd(&g_cnt[d4.y], 1);
        atomicAdd(&g_cnt[d4.z], 1);
        atomicAdd(&g_cnt[d4.w], 1);
    } else {
        for (int i = base; i < E && i < base + 4; i++) {
            int d, s;
            if (g_is32) {
                const int* p = (const int*)ei;
                d = p[i]; s = p[E + i];
            } else {
                const long long* p = (const long long*)ei;
                d = (int)p[i]; s = (int)p[E + i];
            }
            g_dst[i] = d;
            g_src[i] = s;
            atomicAdd(&g_cnt[d], 1);
        }
    }
}

// ---------------------------------------------------------------------------
// Exclusive scan of g_cnt -> g_rowstart.
__global__ void scanA(int n) {
    __shared__ int s[256];
    int t = threadIdx.x, i = blockIdx.x * 256 + t;
    s[t] = (i < n) ? g_cnt[i] : 0;
    __syncthreads();
    for (int off = 128; off; off >>= 1) {
        if (t < off) s[t] += s[t + off];
        __syncthreads();
    }
    if (t == 0) g_bsum[blockIdx.x] = s[0];
}

__global__ void scanB(int nb) {
    __shared__ int s[256];
    int t = threadIdx.x;
    int v = (t < nb) ? g_bsum[t] : 0;
    s[t] = v; __syncthreads();
    for (int off = 1; off < 256; off <<= 1) {
        int a = (t >= off) ? s[t - off] : 0;
        __syncthreads();
        s[t] += a;
        __syncthreads();
    }
    if (t < nb) g_bsum[t] = s[t] - v;
}

__global__ void scanC(int n) {
    __shared__ int s[256];
    int t = threadIdx.x, i = blockIdx.x * 256 + t;
    int v = (i < n) ? g_cnt[i] : 0;
    s[t] = v; __syncthreads();
    for (int off = 1; off < 256; off <<= 1) {
        int a = (t >= off) ? s[t - off] : 0;
        __syncthreads();
        s[t] += a;
        __syncthreads();
    }
    if (i < n) {
        int start = g_bsum[blockIdx.x] + s[t] - v;
        g_rowstart[i] = start;
        g_cursor[i]   = start;
    }
}

// ---------------------------------------------------------------------------
// CSR scatter: index-only entries, NO dependence on gemm -> runs in its shadow.
__global__ void scatter_csr_kernel(int E) {
    int t = blockIdx.x * blockDim.x + threadIdx.x;
    int base = t * 4;
    if (base >= E) return;
    int lim = (base + 4 < E) ? base + 4 : E;
    for (int i = base; i < lim; i++) {
        int d = g_dst[i];
        int pos = atomicAdd(&g_cursor[d], 1);
        g_csr[pos] = make_int2(g_src[i], i);
    }
}

// ---------------------------------------------------------------------------
// Register-tiled GEMM (proven config): 64x64 tile, 4x4 per thread,
// fused score reduction; z stored as fp16 half2.
__global__ void __launch_bounds__(256) gemm_kernel(
    const float* __restrict__ x, const float* __restrict__ W,
    const float* __restrict__ aw, int n_nodes)
{
    __shared__ float xs[64][64];
    __shared__ float Ws[64][64];

    const int tid = threadIdx.x;
    const int tx  = tid & 15;
    const int ty  = tid >> 4;
    const int row0 = blockIdx.x * 64;

    float acc[4][4];
#pragma unroll
    for (int i = 0; i < 4; i++)
#pragma unroll
        for (int j = 0; j < 4; j++) acc[i][j] = 0.f;

    for (int kc = 0; kc < NF; kc += 64) {
#pragma unroll
        for (int it = 0; it < 4; it++) {
            int i = tid + it * 256;
            int r = i >> 4, q = (i & 15) << 2;
            int row = row0 + r;
            float4 v = make_float4(0.f, 0.f, 0.f, 0.f);
            if (row < n_nodes)
                v = *reinterpret_cast<const float4*>(&x[(size_t)row * NF + kc + q]);
            *reinterpret_cast<float4*>(&xs[r][q]) = v;
        }
#pragma unroll
        for (int it = 0; it < 4; it++) {
            int i = tid + it * 256;
            int k = i >> 4, q = (i & 15) << 2;
            *reinterpret_cast<float4*>(&Ws[k][q]) =
                *reinterpret_cast<const float4*>(&W[(size_t)(kc + k) * NH + q]);
        }
        __syncthreads();

#pragma unroll
        for (int k = 0; k < 64; k++) {
            float4 wv = *reinterpret_cast<const float4*>(&Ws[k][tx << 2]);
            float x0 = xs[(ty << 2) + 0][k];
            float x1 = xs[(ty << 2) + 1][k];
            float x2 = xs[(ty << 2) + 2][k];
            float x3 = xs[(ty << 2) + 3][k];
            acc[0][0] = fmaf(x0, wv.x, acc[0][0]); acc[0][1] = fmaf(x0, wv.y, acc[0][1]);
            acc[0][2] = fmaf(x0, wv.z, acc[0][2]); acc[0][3] = fmaf(x0, wv.w, acc[0][3]);
            acc[1][0] = fmaf(x1, wv.x, acc[1][0]); acc[1][1] = fmaf(x1, wv.y, acc[1][1]);
            acc[1][2] = fmaf(x1, wv.z, acc[1][2]); acc[1][3] = fmaf(x1, wv.w, acc[1][3]);
            acc[2][0] = fmaf(x2, wv.x, acc[2][0]); acc[2][1] = fmaf(x2, wv.y, acc[2][1]);
            acc[2][2] = fmaf(x2, wv.z, acc[2][2]); acc[2][3] = fmaf(x2, wv.w, acc[2][3]);
            acc[3][0] = fmaf(x3, wv.x, acc[3][0]); acc[3][1] = fmaf(x3, wv.y, acc[3][1]);
            acc[3][2] = fmaf(x3, wv.z, acc[3][2]); acc[3][3] = fmaf(x3, wv.w, acc[3][3]);
        }
        __syncthreads();
    }

    const float4 a1 = *reinterpret_cast<const float4*>(&aw[tx << 2]);
    const float4 a2 = *reinterpret_cast<const float4*>(&aw[NH + (tx << 2)]);

#pragma unroll
    for (int i = 0; i < 4; i++) {
        int row = row0 + (ty << 2) + i;
        float sd = acc[i][0] * a1.x + acc[i][1] * a1.y + acc[i][2] * a1.z + acc[i][3] * a1.w;
        float ss = acc[i][0] * a2.x + acc[i][1] * a2.y + acc[i][2] * a2.z + acc[i][3] * a2.w;
#pragma unroll
        for (int off = 8; off; off >>= 1) {
            sd += __shfl_down_sync(0xffffffffu, sd, off, 16);
            ss += __shfl_down_sync(0xffffffffu, ss, off, 16);
        }
        if (row < n_nodes) {
            __half2 hp[2];
            hp[0] = __floats2half2_rn(acc[i][0], acc[i][1]);
            hp[1] = __floats2half2_rn(acc[i][2], acc[i][3]);
            *reinterpret_cast<float2*>(&g_zh[(size_t)row * 32 + (tx << 1)]) =
                *reinterpret_cast<const float2*>(hp);
            if (tx == 0) { g_sd[row] = sd; g_ss[row] = ss; }
        }
    }
}

// ---------------------------------------------------------------------------
// One warp per dst node: computes h = exp(leakyrelu(sd[w]+ss[src]+b)) inline,
// accumulates sum(h) and sum(h*z), writes out row + normalized alpha.
__global__ void __launch_bounds__(256) aggregate_csr_kernel(
    float* __restrict__ out, float* __restrict__ alpha,
    const float* __restrict__ ab, int n_nodes)
{
    int w = (blockIdx.x * 256 + threadIdx.x) >> 5;
    int lane = threadIdx.x & 31;
    if (w >= n_nodes) return;

    int start = g_rowstart[w];
    int deg   = g_cnt[w];
    float sdw = g_sd[w] + __ldg(ab);

    float2 acc = make_float2(0.f, 0.f);
    float hs = 0.f;
    for (int e = 0; e < deg; e++) {
        int2 ent = g_csr[start + e];            // broadcast, 1 sector
        float h = sdw + g_ss[ent.x];            // broadcast load
        h = (h >= 0.f) ? h : 0.05f * h;
        h = expf(h);
        hs += h;
        __half2 zh = g_zh[(size_t)ent.x * 32 + lane];
        float2 zv = __half22float2(zh);
        acc.x = fmaf(h, zv.x, acc.x);
        acc.y = fmaf(h, zv.y, acc.y);
    }
    float inv = (hs != 0.f) ? (1.f / hs) : 0.f;
    *reinterpret_cast<float2*>(&out[(size_t)w * NH + lane * 2]) =
        make_float2(acc.x * inv, acc.y * inv);

    // alpha writeback: recompute h per edge (entries/ss are L1-hot).
    for (int k = lane; k < deg; k += 32) {
        int2 ent = g_csr[start + k];
        float h = sdw + g_ss[ent.x];
        h = (h >= 0.f) ? h : 0.05f * h;
        h = expf(h);
        alpha[ent.y] = h * inv;
    }
}

// ---------------------------------------------------------------------------
extern "C" void kernel_launch(void* const* d_in, const int* in_sizes, int n_in,
                              void* d_out, int out_size)
{
    const float* x  = (const float*)d_in[0];
    const void*  ei = d_in[1];
    const float* W  = (const float*)d_in[2];
    const float* aw = (const float*)d_in[3];
    const float* ab = (const float*)d_in[4];

    const int n_nodes = in_sizes[0] / NF;
    const int E       = in_sizes[1] / 2;
    const int nb      = (n_nodes + 255) / 256;

    float* out   = (float*)d_out;
    float* alpha = out + (size_t)n_nodes * NH;

    static cudaStream_t s_side = nullptr;
    static cudaEvent_t  ev_fork = nullptr, ev_join = nullptr;
    if (!s_side) {
        cudaStreamCreateWithFlags(&s_side, cudaStreamNonBlocking);
        cudaEventCreateWithFlags(&ev_fork, cudaEventDisableTiming);
        cudaEventCreateWithFlags(&ev_join, cudaEventDisableTiming);
    }

    // Fork: gemm on the side stream.
    cudaEventRecord(ev_fork, (cudaStream_t)0);
    cudaStreamWaitEvent(s_side, ev_fork, 0);
    gemm_kernel<<<(n_nodes + 63) / 64, 256, 0, s_side>>>(x, W, aw, n_nodes);
    cudaEventRecord(ev_join, s_side);

    // Main stream: full edge pipeline incl. CSR scatter (gemm-independent).
    zero_kernel<<<(n_nodes + 1023) / 1024, 1024>>>(n_nodes);
    detect_kernel<<<1, 256>>>((const int*)ei, in_sizes[1]);
    convert_kernel<<<(E / 4 + 255) / 256, 256>>>(ei, E);
    scanA<<<nb, 256>>>(n_nodes);
    scanB<<<1, 256>>>(nb);
    scanC<<<nb, 256>>>(n_nodes);
    scatter_csr_kernel<<<(E / 4 + 255) / 256, 256>>>(E);

    // Join: only the aggregate needs both gemm and the CSR.
    cudaStreamWaitEvent((cudaStream_t)0, ev_join, 0);

    long long tot = (long long)n_nodes * 32;
    aggregate_csr_kernel<<<(int)((tot + 255) / 256), 256>>>(out, alpha, ab, n_nodes);
}

// round 16
// speedup vs baseline: 1.1541x; 1.1541x over previous
#include <cuda_runtime.h>
#include <cuda_fp16.h>
#include <cstdint>

#define NF 128
#define NH 64
#define MAXN 50000
#define MAXE 800000

// Scratch (allocation-free rule: __device__ globals)
__device__ __half2 g_zh[(size_t)MAXN * (NH / 2)];   // 6.4 MB, z in fp16
__device__ float g_sd[MAXN];
__device__ float g_ss[MAXN];
__device__ float g_w1[NF];
__device__ float g_w2[NF];
__device__ int   g_dst[MAXE];
__device__ int   g_src[MAXE];
__device__ int   g_cnt[MAXN];
__device__ int   g_rowstart[MAXN];
__device__ int   g_cursor[MAXN];
__device__ int   g_bsum[1024];
__device__ int4  g_csr[MAXE];              // {src, eidx, h_bits, 0}
__device__ int   g_is32;

// ---------------------------------------------------------------------------
// zero g_cnt; block 0 additionally probes edge_index dtype (int64 high words
// are all zero for indices < 2^31). g_is32 written unconditionally by block 0.
__global__ void zero_detect_kernel(const int* __restrict__ w, int nelem, int n_nodes) {
    int i = blockIdx.x * blockDim.x + threadIdx.x;
    if (i < n_nodes) g_cnt[i] = 0;
    if (blockIdx.x == 0) {
        int found = 0;
        int lim = nelem / 2;
        if (lim > 4096) lim = 4096;
        for (int j = threadIdx.x; j < lim; j += blockDim.x)
            found |= w[2 * j + 1];
        int any = __syncthreads_or(found);
        if (threadIdx.x == 0) g_is32 = any ? 1 : 0;
    }
}

// Convert to int32 + histogram, 4 edges per thread, vector loads/stores.
__global__ void convert_kernel(const void* __restrict__ ei, int E) {
    int t = blockIdx.x * blockDim.x + threadIdx.x;
    int base = t * 4;
    if (base >= E) return;
    if (base + 3 < E && (E & 3) == 0) {
        int4 d4, s4;
        if (g_is32) {
            const int4* p = (const int4*)ei;
            d4 = p[base >> 2];
            s4 = p[(E + base) >> 2];
        } else {
            const longlong2* p = (const longlong2*)ei;
            longlong2 a0 = p[(base >> 1)];
            longlong2 a1 = p[(base >> 1) + 1];
            longlong2 b0 = p[((E + base) >> 1)];
            longlong2 b1 = p[((E + base) >> 1) + 1];
            d4 = make_int4((int)a0.x, (int)a0.y, (int)a1.x, (int)a1.y);
            s4 = make_int4((int)b0.x, (int)b0.y, (int)b1.x, (int)b1.y);
        }
        *reinterpret_cast<int4*>(&g_dst[base]) = d4;
        *reinterpret_cast<int4*>(&g_src[base]) = s4;
        atomicAdd(&g_cnt[d4.x], 1);
        atomicAdd(&g_cnt[d4.y], 1);
        atomicAdd(&g_cnt[d4.z], 1);
        atomicAdd(&g_cnt[d4.w], 1);
    } else {
        for (int i = base; i < E && i < base + 4; i++) {
            int d, s;
            if (g_is32) {
                const int* p = (const int*)ei;
                d = p[i]; s = p[E + i];
            } else {
                const long long* p = (const long long*)ei;
                d = (int)p[i]; s = (int)p[E + i];
            }
            g_dst[i] = d;
            g_src[i] = s;
            atomicAdd(&g_cnt[d], 1);
        }
    }
}

// ---------------------------------------------------------------------------
// Exclusive scan of g_cnt -> g_rowstart.
__global__ void scanA(int n) {
    __shared__ int s[256];
    int t = threadIdx.x, i = blockIdx.x * 256 + t;
    s[t] = (i < n) ? g_cnt[i] : 0;
    __syncthreads();
    for (int off = 128; off; off >>= 1) {
        if (t < off) s[t] += s[t + off];
        __syncthreads();
    }
    if (t == 0) g_bsum[blockIdx.x] = s[0];
}

__global__ void scanB(int nb) {
    __shared__ int s[256];
    int t = threadIdx.x;
    int v = (t < nb) ? g_bsum[t] : 0;
    s[t] = v; __syncthreads();
    for (int off = 1; off < 256; off <<= 1) {
        int a = (t >= off) ? s[t - off] : 0;
        __syncthreads();
        s[t] += a;
        __syncthreads();
    }
    if (t < nb) g_bsum[t] = s[t] - v;
}

__global__ void scanC(int n) {
    __shared__ int s[256];
    int t = threadIdx.x, i = blockIdx.x * 256 + t;
    int v = (i < n) ? g_cnt[i] : 0;
    s[t] = v; __syncthreads();
    for (int off = 1; off < 256; off <<= 1) {
        int a = (t >= off) ? s[t - off] : 0;
        __syncthreads();
        s[t] += a;
        __syncthreads();
    }
    if (i < n) {
        int start = g_bsum[blockIdx.x] + s[t] - v;
        g_rowstart[i] = start;
        g_cursor[i]   = start;
    }
}

// ---------------------------------------------------------------------------
// w1 = W @ a_w[:H], w2 = W @ a_w[H:]  (128 dots of length 64; tiny).
__global__ void wvec_kernel(const float* __restrict__ W,
                            const float* __restrict__ aw) {
    int k = threadIdx.x;          // 0..127
    if (k >= NF) return;
    float s1 = 0.f, s2 = 0.f;
#pragma unroll 16
    for (int n = 0; n < NH; n++) {
        float wkn = __ldg(&W[k * NH + n]);
        s1 = fmaf(wkn, __ldg(&aw[n]), s1);
        s2 = fmaf(wkn, __ldg(&aw[NH + n]), s2);
    }
    g_w1[k] = s1;
    g_w2[k] = s2;
}

// sd[i] = x_i . w1, ss[i] = x_i . w2  — warp per row, streaming x once.
// Independent of the GEMM: uses the identity z.a1 = x.(W a1).
__global__ void __launch_bounds__(256) score_kernel(
    const float* __restrict__ x, int n_nodes)
{
    int w = (blockIdx.x * 256 + threadIdx.x) >> 5;
    int lane = threadIdx.x & 31;
    if (w >= n_nodes) return;
    float4 xv = *reinterpret_cast<const float4*>(&x[(size_t)w * NF + lane * 4]);
    float4 w1 = *reinterpret_cast<const float4*>(&g_w1[lane * 4]);
    float4 w2 = *reinterpret_cast<const float4*>(&g_w2[lane * 4]);
    float sd = xv.x * w1.x + xv.y * w1.y + xv.z * w1.z + xv.w * w1.w;
    float ss = xv.x * w2.x + xv.y * w2.y + xv.z * w2.z + xv.w * w2.w;
#pragma unroll
    for (int off = 16; off; off >>= 1) {
        sd += __shfl_down_sync(0xffffffffu, sd, off);
        ss += __shfl_down_sync(0xffffffffu, ss, off);
    }
    if (lane == 0) { g_sd[w] = sd; g_ss[w] = ss; }
}

// ---------------------------------------------------------------------------
// Per-edge score + CSR scatter (needs scores + scan chain, NOT the gemm).
__global__ void edge_scatter_kernel(const float* __restrict__ ab, int E) {
    int e = blockIdx.x * blockDim.x + threadIdx.x;
    if (e >= E) return;
    int d = g_dst[e], s = g_src[e];
    float h = g_sd[d] + g_ss[s] + __ldg(ab);
    h = (h >= 0.f) ? h : 0.05f * h;
    h = expf(h);
    int pos = atomicAdd(&g_cursor[d], 1);
    g_csr[pos] = make_int4(s, e, __float_as_int(h), 0);
}

// ---------------------------------------------------------------------------
// Register-tiled GEMM: 64x64 tile, 4x4 per thread; z stored fp16.
// Score epilogue removed (scores computed by score_kernel).
__global__ void __launch_bounds__(256) gemm_kernel(
    const float* __restrict__ x, const float* __restrict__ W, int n_nodes)
{
    __shared__ float xs[64][64];
    __shared__ float Ws[64][64];

    const int tid = threadIdx.x;
    const int tx  = tid & 15;
    const int ty  = tid >> 4;
    const int row0 = blockIdx.x * 64;

    float acc[4][4];
#pragma unroll
    for (int i = 0; i < 4; i++)
#pragma unroll
        for (int j = 0; j < 4; j++) acc[i][j] = 0.f;

    for (int kc = 0; kc < NF; kc += 64) {
#pragma unroll
        for (int it = 0; it < 4; it++) {
            int i = tid + it * 256;
            int r = i >> 4, q = (i & 15) << 2;
            int row = row0 + r;
            float4 v = make_float4(0.f, 0.f, 0.f, 0.f);
            if (row < n_nodes)
                v = *reinterpret_cast<const float4*>(&x[(size_t)row * NF + kc + q]);
            *reinterpret_cast<float4*>(&xs[r][q]) = v;
        }
#pragma unroll
        for (int it = 0; it < 4; it++) {
            int i = tid + it * 256;
            int k = i >> 4, q = (i & 15) << 2;
            *reinterpret_cast<float4*>(&Ws[k][q]) =
                *reinterpret_cast<const float4*>(&W[(size_t)(kc + k) * NH + q]);
        }
        __syncthreads();

#pragma unroll
        for (int k = 0; k < 64; k++) {
            float4 wv = *reinterpret_cast<const float4*>(&Ws[k][tx << 2]);
            float x0 = xs[(ty << 2) + 0][k];
            float x1 = xs[(ty << 2) + 1][k];
            float x2 = xs[(ty << 2) + 2][k];
            float x3 = xs[(ty << 2) + 3][k];
            acc[0][0] = fmaf(x0, wv.x, acc[0][0]); acc[0][1] = fmaf(x0, wv.y, acc[0][1]);
            acc[0][2] = fmaf(x0, wv.z, acc[0][2]); acc[0][3] = fmaf(x0, wv.w, acc[0][3]);
            acc[1][0] = fmaf(x1, wv.x, acc[1][0]); acc[1][1] = fmaf(x1, wv.y, acc[1][1]);
            acc[1][2] = fmaf(x1, wv.z, acc[1][2]); acc[1][3] = fmaf(x1, wv.w, acc[1][3]);
            acc[2][0] = fmaf(x2, wv.x, acc[2][0]); acc[2][1] = fmaf(x2, wv.y, acc[2][1]);
            acc[2][2] = fmaf(x2, wv.z, acc[2][2]); acc[2][3] = fmaf(x2, wv.w, acc[2][3]);
            acc[3][0] = fmaf(x3, wv.x, acc[3][0]); acc[3][1] = fmaf(x3, wv.y, acc[3][1]);
            acc[3][2] = fmaf(x3, wv.z, acc[3][2]); acc[3][3] = fmaf(x3, wv.w, acc[3][3]);
        }
        __syncthreads();
    }

#pragma unroll
    for (int i = 0; i < 4; i++) {
        int row = row0 + (ty << 2) + i;
        if (row < n_nodes) {
            __half2 hp[2];
            hp[0] = __floats2half2_rn(acc[i][0], acc[i][1]);
            hp[1] = __floats2half2_rn(acc[i][2], acc[i][3]);
            *reinterpret_cast<float2*>(&g_zh[(size_t)row * 32 + (tx << 1)]) =
                *reinterpret_cast<const float2*>(hp);
        }
    }
}

// ---------------------------------------------------------------------------
// One warp per dst node, z gathered as half2, h from csr entry.
__global__ void __launch_bounds__(256) aggregate_csr_kernel(
    float* __restrict__ out, float* __restrict__ alpha, int n_nodes)
{
    int w = (blockIdx.x * 256 + threadIdx.x) >> 5;
    int lane = threadIdx.x & 31;
    if (w >= n_nodes) return;

    int start = g_rowstart[w];
    int deg   = g_cnt[w];

    float2 acc = make_float2(0.f, 0.f);
    float hs = 0.f;
    for (int e = 0; e < deg; e++) {
        int4 ent = g_csr[start + e];            // broadcast, 1 sector
        float h = __int_as_float(ent.z);
        hs += h;
        __half2 zh = g_zh[(size_t)ent.x * 32 + lane];
        float2 zv = __half22float2(zh);
        acc.x = fmaf(h, zv.x, acc.x);
        acc.y = fmaf(h, zv.y, acc.y);
    }
    float inv = (hs != 0.f) ? (1.f / hs) : 0.f;
    *reinterpret_cast<float2*>(&out[(size_t)w * NH + lane * 2]) =
        make_float2(acc.x * inv, acc.y * inv);

    for (int e = lane; e < deg; e += 32) {
        int4 ent = g_csr[start + e];            // L1 hit
        alpha[ent.y] = __int_as_float(ent.z) * inv;
    }
}

// ---------------------------------------------------------------------------
extern "C" void kernel_launch(void* const* d_in, const int* in_sizes, int n_in,
                              void* d_out, int out_size)
{
    const float* x  = (const float*)d_in[0];
    const void*  ei = d_in[1];
    const float* W  = (const float*)d_in[2];
    const float* aw = (const float*)d_in[3];
    const float* ab = (const float*)d_in[4];

    const int n_nodes = in_sizes[0] / NF;
    const int E       = in_sizes[1] / 2;
    const int nb      = (n_nodes + 255) / 256;

    float* out   = (float*)d_out;
    float* alpha = out + (size_t)n_nodes * NH;

    static cudaStream_t s_gemm = nullptr, s_score = nullptr;
    static cudaEvent_t  ev_fork = nullptr, ev_gemm = nullptr, ev_score = nullptr;
    if (!s_gemm) {
        cudaStreamCreateWithFlags(&s_gemm, cudaStreamNonBlocking);
        cudaStreamCreateWithFlags(&s_score, cudaStreamNonBlocking);
        cudaEventCreateWithFlags(&ev_fork,  cudaEventDisableTiming);
        cudaEventCreateWithFlags(&ev_gemm,  cudaEventDisableTiming);
        cudaEventCreateWithFlags(&ev_score, cudaEventDisableTiming);
    }

    cudaEventRecord(ev_fork, (cudaStream_t)0);

    // Branch 1: the big GEMM (z only).
    cudaStreamWaitEvent(s_gemm, ev_fork, 0);
    gemm_kernel<<<(n_nodes + 63) / 64, 256, 0, s_gemm>>>(x, W, n_nodes);
    cudaEventRecord(ev_gemm, s_gemm);

    // Branch 2: scores straight from x (sd = x.(W a1), ss = x.(W a2)).
    cudaStreamWaitEvent(s_score, ev_fork, 0);
    wvec_kernel<<<1, 128, 0, s_score>>>(W, aw);
    score_kernel<<<(n_nodes * 32 + 255) / 256, 256, 0, s_score>>>(x, n_nodes);
    cudaEventRecord(ev_score, s_score);

    // Branch 3 (main): index preprocessing.
    zero_detect_kernel<<<(n_nodes + 255) / 256, 256>>>((const int*)ei,
                                                       in_sizes[1], n_nodes);
    convert_kernel<<<(E / 4 + 255) / 256, 256>>>(ei, E);
    scanA<<<nb, 256>>>(n_nodes);
    scanB<<<1, 256>>>(nb);
    scanC<<<nb, 256>>>(n_nodes);

    // Scatter needs scores + scan chain (still inside the gemm's shadow).
    cudaStreamWaitEvent((cudaStream_t)0, ev_score, 0);
    edge_scatter_kernel<<<(E + 255) / 256, 256>>>(ab, E);

    // Aggregate is the only gemm-dependent stage.
    cudaStreamWaitEvent((cudaStream_t)0, ev_gemm, 0);
    long long tot = (long long)n_nodes * 32;
    aggregate_csr_kernel<<<(int)((tot + 255) / 256), 256>>>(out, alpha, n_nodes);
}

// round 17
// speedup vs baseline: 1.1715x; 1.0150x over previous
#include <cuda_runtime.h>
#include <cuda_fp16.h>
#include <cstdint>

#define NF 128
#define NH 64
#define MAXN 50000
#define MAXE 800000

// Scratch (allocation-free rule: __device__ globals)
__device__ __half2 g_zh[(size_t)MAXN * (NH / 2)];   // 6.4 MB, z in fp16
__device__ float g_sd[MAXN];
__device__ float g_ss[MAXN];
__device__ int   g_dst[MAXE];
__device__ int   g_src[MAXE];
__device__ int   g_cnt[MAXN];
__device__ int   g_rowstart[MAXN];
__device__ int   g_cursor[MAXN];
__device__ int   g_bsum[1024];
__device__ int4  g_csr[MAXE];              // {src, eidx, h_bits, 0}
__device__ int   g_is32;

// ---------------------------------------------------------------------------
// zero g_cnt; block 0 probes edge_index dtype (int64 high words all zero).
__global__ void zero_detect_kernel(const int* __restrict__ w, int nelem, int n_nodes) {
    int i = blockIdx.x * blockDim.x + threadIdx.x;
    if (i < n_nodes) g_cnt[i] = 0;
    if (blockIdx.x == 0) {
        int found = 0;
        int lim = nelem / 2;
        if (lim > 4096) lim = 4096;
        for (int j = threadIdx.x; j < lim; j += blockDim.x)
            found |= w[2 * j + 1];
        int any = __syncthreads_or(found);
        if (threadIdx.x == 0) g_is32 = any ? 1 : 0;
    }
}

// Convert to int32 + histogram, 4 edges per thread, vector loads/stores.
__global__ void convert_kernel(const void* __restrict__ ei, int E) {
    int t = blockIdx.x * blockDim.x + threadIdx.x;
    int base = t * 4;
    if (base >= E) return;
    if (base + 3 < E && (E & 3) == 0) {
        int4 d4, s4;
        if (g_is32) {
            const int4* p = (const int4*)ei;
            d4 = p[base >> 2];
            s4 = p[(E + base) >> 2];
        } else {
            const longlong2* p = (const longlong2*)ei;
            longlong2 a0 = p[(base >> 1)];
            longlong2 a1 = p[(base >> 1) + 1];
            longlong2 b0 = p[((E + base) >> 1)];
            longlong2 b1 = p[((E + base) >> 1) + 1];
            d4 = make_int4((int)a0.x, (int)a0.y, (int)a1.x, (int)a1.y);
            s4 = make_int4((int)b0.x, (int)b0.y, (int)b1.x, (int)b1.y);
        }
        *reinterpret_cast<int4*>(&g_dst[base]) = d4;
        *reinterpret_cast<int4*>(&g_src[base]) = s4;
        atomicAdd(&g_cnt[d4.x], 1);
        atomicAdd(&g_cnt[d4.y], 1);
        atomicAdd(&g_cnt[d4.z], 1);
        atomicAdd(&g_cnt[d4.w], 1);
    } else {
        for (int i = base; i < E && i < base + 4; i++) {
            int d, s;
            if (g_is32) {
                const int* p = (const int*)ei;
                d = p[i]; s = p[E + i];
            } else {
                const long long* p = (const long long*)ei;
                d = (int)p[i]; s = (int)p[E + i];
            }
            g_dst[i] = d;
            g_src[i] = s;
            atomicAdd(&g_cnt[d], 1);
        }
    }
}

// ---------------------------------------------------------------------------
// Exclusive scan of g_cnt -> g_rowstart.
__global__ void scanA(int n) {
    __shared__ int s[256];
    int t = threadIdx.x, i = blockIdx.x * 256 + t;
    s[t] = (i < n) ? g_cnt[i] : 0;
    __syncthreads();
    for (int off = 128; off; off >>= 1) {
        if (t < off) s[t] += s[t + off];
        __syncthreads();
    }
    if (t == 0) g_bsum[blockIdx.x] = s[0];
}

__global__ void scanB(int nb) {
    __shared__ int s[256];
    int t = threadIdx.x;
    int v = (t < nb) ? g_bsum[t] : 0;
    s[t] = v; __syncthreads();
    for (int off = 1; off < 256; off <<= 1) {
        int a = (t >= off) ? s[t - off] : 0;
        __syncthreads();
        s[t] += a;
        __syncthreads();
    }
    if (t < nb) g_bsum[t] = s[t] - v;
}

__global__ void scanC(int n) {
    __shared__ int s[256];
    int t = threadIdx.x, i = blockIdx.x * 256 + t;
    int v = (i < n) ? g_cnt[i] : 0;
    s[t] = v; __syncthreads();
    for (int off = 1; off < 256; off <<= 1) {
        int a = (t >= off) ? s[t - off] : 0;
        __syncthreads();
        s[t] += a;
        __syncthreads();
    }
    if (i < n) {
        int start = g_bsum[blockIdx.x] + s[t] - v;
        g_rowstart[i] = start;
        g_cursor[i]   = start;
    }
}

// ---------------------------------------------------------------------------
// Register-tiled GEMM (proven): 64x64 tile, 4x4/thread, fused score epilogue,
// z stored fp16.
__global__ void __launch_bounds__(256) gemm_kernel(
    const float* __restrict__ x, const float* __restrict__ W,
    const float* __restrict__ aw, int n_nodes)
{
    __shared__ float xs[64][64];
    __shared__ float Ws[64][64];

    const int tid = threadIdx.x;
    const int tx  = tid & 15;
    const int ty  = tid >> 4;
    const int row0 = blockIdx.x * 64;

    float acc[4][4];
#pragma unroll
    for (int i = 0; i < 4; i++)
#pragma unroll
        for (int j = 0; j < 4; j++) acc[i][j] = 0.f;

    for (int kc = 0; kc < NF; kc += 64) {
#pragma unroll
        for (int it = 0; it < 4; it++) {
            int i = tid + it * 256;
            int r = i >> 4, q = (i & 15) << 2;
            int row = row0 + r;
            float4 v = make_float4(0.f, 0.f, 0.f, 0.f);
            if (row < n_nodes)
                v = *reinterpret_cast<const float4*>(&x[(size_t)row * NF + kc + q]);
            *reinterpret_cast<float4*>(&xs[r][q]) = v;
        }
#pragma unroll
        for (int it = 0; it < 4; it++) {
            int i = tid + it * 256;
            int k = i >> 4, q = (i & 15) << 2;
            *reinterpret_cast<float4*>(&Ws[k][q]) =
                *reinterpret_cast<const float4*>(&W[(size_t)(kc + k) * NH + q]);
        }
        __syncthreads();

#pragma unroll
        for (int k = 0; k < 64; k++) {
            float4 wv = *reinterpret_cast<const float4*>(&Ws[k][tx << 2]);
            float x0 = xs[(ty << 2) + 0][k];
            float x1 = xs[(ty << 2) + 1][k];
            float x2 = xs[(ty << 2) + 2][k];
            float x3 = xs[(ty << 2) + 3][k];
            acc[0][0] = fmaf(x0, wv.x, acc[0][0]); acc[0][1] = fmaf(x0, wv.y, acc[0][1]);
            acc[0][2] = fmaf(x0, wv.z, acc[0][2]); acc[0][3] = fmaf(x0, wv.w, acc[0][3]);
            acc[1][0] = fmaf(x1, wv.x, acc[1][0]); acc[1][1] = fmaf(x1, wv.y, acc[1][1]);
            acc[1][2] = fmaf(x1, wv.z, acc[1][2]); acc[1][3] = fmaf(x1, wv.w, acc[1][3]);
            acc[2][0] = fmaf(x2, wv.x, acc[2][0]); acc[2][1] = fmaf(x2, wv.y, acc[2][1]);
            acc[2][2] = fmaf(x2, wv.z, acc[2][2]); acc[2][3] = fmaf(x2, wv.w, acc[2][3]);
            acc[3][0] = fmaf(x3, wv.x, acc[3][0]); acc[3][1] = fmaf(x3, wv.y, acc[3][1]);
            acc[3][2] = fmaf(x3, wv.z, acc[3][2]); acc[3][3] = fmaf(x3, wv.w, acc[3][3]);
        }
        __syncthreads();
    }

    const float4 a1 = *reinterpret_cast<const float4*>(&aw[tx << 2]);
    const float4 a2 = *reinterpret_cast<const float4*>(&aw[NH + (tx << 2)]);

#pragma unroll
    for (int i = 0; i < 4; i++) {
        int row = row0 + (ty << 2) + i;
        float sd = acc[i][0] * a1.x + acc[i][1] * a1.y + acc[i][2] * a1.z + acc[i][3] * a1.w;
        float ss = acc[i][0] * a2.x + acc[i][1] * a2.y + acc[i][2] * a2.z + acc[i][3] * a2.w;
#pragma unroll
        for (int off = 8; off; off >>= 1) {
            sd += __shfl_down_sync(0xffffffffu, sd, off, 16);
            ss += __shfl_down_sync(0xffffffffu, ss, off, 16);
        }
        if (row < n_nodes) {
            __half2 hp[2];
            hp[0] = __floats2half2_rn(acc[i][0], acc[i][1]);
            hp[1] = __floats2half2_rn(acc[i][2], acc[i][3]);
            *reinterpret_cast<float2*>(&g_zh[(size_t)row * 32 + (tx << 1)]) =
                *reinterpret_cast<const float2*>(hp);
            if (tx == 0) { g_sd[row] = sd; g_ss[row] = ss; }
        }
    }
}

// ---------------------------------------------------------------------------
// Per-edge score + CSR scatter, 4 edges/thread with int4 index loads so the
// 8 sd/ss gathers issue back-to-back (MLP 8).
__global__ void edge_scatter_kernel(const float* __restrict__ ab, int E) {
    int t = blockIdx.x * blockDim.x + threadIdx.x;
    int base = t * 4;
    if (base >= E) return;
    float b = __ldg(ab);
    if (base + 3 < E) {
        int4 d4 = *reinterpret_cast<const int4*>(&g_dst[base]);
        int4 s4 = *reinterpret_cast<const int4*>(&g_src[base]);
        float sd0 = g_sd[d4.x], sd1 = g_sd[d4.y], sd2 = g_sd[d4.z], sd3 = g_sd[d4.w];
        float ss0 = g_ss[s4.x], ss1 = g_ss[s4.y], ss2 = g_ss[s4.z], ss3 = g_ss[s4.w];
        float h0 = sd0 + ss0 + b; h0 = (h0 >= 0.f) ? h0 : 0.05f * h0; h0 = expf(h0);
        float h1 = sd1 + ss1 + b; h1 = (h1 >= 0.f) ? h1 : 0.05f * h1; h1 = expf(h1);
        float h2 = sd2 + ss2 + b; h2 = (h2 >= 0.f) ? h2 : 0.05f * h2; h2 = expf(h2);
        float h3 = sd3 + ss3 + b; h3 = (h3 >= 0.f) ? h3 : 0.05f * h3; h3 = expf(h3);
        int p0 = atomicAdd(&g_cursor[d4.x], 1);
        int p1 = atomicAdd(&g_cursor[d4.y], 1);
        int p2 = atomicAdd(&g_cursor[d4.z], 1);
        int p3 = atomicAdd(&g_cursor[d4.w], 1);
        g_csr[p0] = make_int4(s4.x, base + 0, __float_as_int(h0), 0);
        g_csr[p1] = make_int4(s4.y, base + 1, __float_as_int(h1), 0);
        g_csr[p2] = make_int4(s4.z, base + 2, __float_as_int(h2), 0);
        g_csr[p3] = make_int4(s4.w, base + 3, __float_as_int(h3), 0);
    } else {
        for (int i = base; i < E; i++) {
            int d = g_dst[i], s = g_src[i];
            float h = g_sd[d] + g_ss[s] + b;
            h = (h >= 0.f) ? h : 0.05f * h;
            h = expf(h);
            int pos = atomicAdd(&g_cursor[d], 1);
            g_csr[pos] = make_int4(s, i, __float_as_int(h), 0);
        }
    }
}

// ---------------------------------------------------------------------------
// One warp per dst node; deg-loop unrolled x4 with batched independent loads.
__global__ void __launch_bounds__(256) aggregate_csr_kernel(
    float* __restrict__ out, float* __restrict__ alpha, int n_nodes)
{
    int w = (blockIdx.x * 256 + threadIdx.x) >> 5;
    int lane = threadIdx.x & 31;
    if (w >= n_nodes) return;

    int start = g_rowstart[w];
    int deg   = g_cnt[w];

    float2 acc = make_float2(0.f, 0.f);
    float hs = 0.f;
    int e = 0;
    for (; e + 4 <= deg; e += 4) {
        int4 n0 = g_csr[start + e];
        int4 n1 = g_csr[start + e + 1];
        int4 n2 = g_csr[start + e + 2];
        int4 n3 = g_csr[start + e + 3];
        __half2 z0 = g_zh[(size_t)n0.x * 32 + lane];
        __half2 z1 = g_zh[(size_t)n1.x * 32 + lane];
        __half2 z2 = g_zh[(size_t)n2.x * 32 + lane];
        __half2 z3 = g_zh[(size_t)n3.x * 32 + lane];
        float h0 = __int_as_float(n0.z), h1 = __int_as_float(n1.z);
        float h2 = __int_as_float(n2.z), h3 = __int_as_float(n3.z);
        hs += (h0 + h1) + (h2 + h3);
        float2 v0 = __half22float2(z0), v1 = __half22float2(z1);
        float2 v2 = __half22float2(z2), v3 = __half22float2(z3);
        acc.x = fmaf(h0, v0.x, acc.x); acc.y = fmaf(h0, v0.y, acc.y);
        acc.x = fmaf(h1, v1.x, acc.x); acc.y = fmaf(h1, v1.y, acc.y);
        acc.x = fmaf(h2, v2.x, acc.x); acc.y = fmaf(h2, v2.y, acc.y);
        acc.x = fmaf(h3, v3.x, acc.x); acc.y = fmaf(h3, v3.y, acc.y);
    }
    for (; e < deg; e++) {
        int4 ent = g_csr[start + e];
        float h = __int_as_float(ent.z);
        hs += h;
        float2 zv = __half22float2(g_zh[(size_t)ent.x * 32 + lane]);
        acc.x = fmaf(h, zv.x, acc.x);
        acc.y = fmaf(h, zv.y, acc.y);
    }
    float inv = (hs != 0.f) ? (1.f / hs) : 0.f;
    *reinterpret_cast<float2*>(&out[(size_t)w * NH + lane * 2]) =
        make_float2(acc.x * inv, acc.y * inv);

    for (int k = lane; k < deg; k += 32) {
        int4 ent = g_csr[start + k];            // L1 hit
        alpha[ent.y] = __int_as_float(ent.z) * inv;
    }
}

// ---------------------------------------------------------------------------
extern "C" void kernel_launch(void* const* d_in, const int* in_sizes, int n_in,
                              void* d_out, int out_size)
{
    const float* x  = (const float*)d_in[0];
    const void*  ei = d_in[1];
    const float* W  = (const float*)d_in[2];
    const float* aw = (const float*)d_in[3];
    const float* ab = (const float*)d_in[4];

    const int n_nodes = in_sizes[0] / NF;
    const int E       = in_sizes[1] / 2;
    const int nb      = (n_nodes + 255) / 256;

    float* out   = (float*)d_out;
    float* alpha = out + (size_t)n_nodes * NH;

    static cudaStream_t s_side = nullptr;
    static cudaEvent_t  ev_fork = nullptr, ev_join = nullptr;
    if (!s_side) {
        cudaStreamCreateWithFlags(&s_side, cudaStreamNonBlocking);
        cudaEventCreateWithFlags(&ev_fork, cudaEventDisableTiming);
        cudaEventCreateWithFlags(&ev_join, cudaEventDisableTiming);
    }

    // Fork: gemm (z + fused scores) on the side stream.
    cudaEventRecord(ev_fork, (cudaStream_t)0);
    cudaStreamWaitEvent(s_side, ev_fork, 0);
    gemm_kernel<<<(n_nodes + 63) / 64, 256, 0, s_side>>>(x, W, aw, n_nodes);
    cudaEventRecord(ev_join, s_side);

    // Main stream: edge-index preprocessing, overlapped with gemm.
    zero_detect_kernel<<<(n_nodes + 255) / 256, 256>>>((const int*)ei,
                                                       in_sizes[1], n_nodes);
    convert_kernel<<<(E / 4 + 255) / 256, 256>>>(ei, E);
    scanA<<<nb, 256>>>(n_nodes);
    scanB<<<1, 256>>>(nb);
    scanC<<<nb, 256>>>(n_nodes);

    // Join: scatter needs gemm scores + scan chain.
    cudaStreamWaitEvent((cudaStream_t)0, ev_join, 0);

    edge_scatter_kernel<<<(E / 4 + 255) / 256, 256>>>(ab, E);

    long long tot = (long long)n_nodes * 32;
    aggregate_csr_kernel<<<(int)((tot + 255) / 256), 256>>>(out, alpha, n_nodes);
}